// round 1
// baseline (speedup 1.0000x reference)
#include <cuda_runtime.h>

#define Lf 16
#define Cc 64
#define Hh 128
#define Ww 128
#define HW (Hh*Ww)
#define CHW (Cc*HW)
#define LCHW (Lf*CHW)
#define NCHUNK 64

// -------- scratch (static device globals; no runtime allocation) --------
__device__ float g_V[LCHW];                 // V tensor          (67 MB)
__device__ float g_F1[(size_t)Lf*2*Cc*HW];  // FFN hidden        (134 MB)
__device__ float g_B[Lf*HW];                // pre-softmax scores
__device__ float g_P[Lf*HW];                // softmax probs
__device__ float g_stats[2*Lf];             // per-frame mean, rstd
__device__ float g_part[Lf*NCHUNK*2];       // LN partial sums
__device__ float g_Wfk[Cc*25];              // folded conv weights
__device__ float g_bw[25];                  // folded conv bias taps

// ---------------- LayerNorm statistics (two-stage) ----------------
__global__ void ln_partial_k(const float* __restrict__ x) {
    int l = blockIdx.y;
    int chunk = blockIdx.x;
    const float4* xf = reinterpret_cast<const float4*>(x + (size_t)l * CHW);
    int base = chunk * (CHW / NCHUNK / 4);
    float s = 0.f, s2 = 0.f;
    #pragma unroll 4
    for (int i = threadIdx.x; i < CHW / NCHUNK / 4; i += 256) {
        float4 v = xf[base + i];
        s  += v.x + v.y + v.z + v.w;
        s2 += v.x*v.x + v.y*v.y + v.z*v.z + v.w*v.w;
    }
    #pragma unroll
    for (int o = 16; o > 0; o >>= 1) {
        s  += __shfl_down_sync(0xffffffffu, s,  o);
        s2 += __shfl_down_sync(0xffffffffu, s2, o);
    }
    __shared__ float sh[8], sh2[8];
    int w = threadIdx.x >> 5, lane = threadIdx.x & 31;
    if (lane == 0) { sh[w] = s; sh2[w] = s2; }
    __syncthreads();
    if (w == 0) {
        s  = lane < 8 ? sh[lane]  : 0.f;
        s2 = lane < 8 ? sh2[lane] : 0.f;
        #pragma unroll
        for (int o = 4; o > 0; o >>= 1) {
            s  += __shfl_down_sync(0xffffffffu, s,  o);
            s2 += __shfl_down_sync(0xffffffffu, s2, o);
        }
        if (lane == 0) {
            g_part[(l*NCHUNK + chunk)*2]     = s;
            g_part[(l*NCHUNK + chunk)*2 + 1] = s2;
        }
    }
}

__global__ void ln_final_k() {
    int w = threadIdx.x >> 5, lane = threadIdx.x & 31;  // w = frame (16 warps)
    float s  = g_part[(w*NCHUNK + lane)*2]     + g_part[(w*NCHUNK + lane + 32)*2];
    float s2 = g_part[(w*NCHUNK + lane)*2 + 1] + g_part[(w*NCHUNK + lane + 32)*2 + 1];
    #pragma unroll
    for (int o = 16; o > 0; o >>= 1) {
        s  += __shfl_down_sync(0xffffffffu, s,  o);
        s2 += __shfl_down_sync(0xffffffffu, s2, o);
    }
    if (lane == 0) {
        float mu  = s / (float)CHW;
        float var = s2 / (float)CHW - mu*mu;
        g_stats[w*2]     = mu;
        g_stats[w*2 + 1] = rsqrtf(var + 1e-5f);
    }
}

// ---------------- Fold 5x5 conv through Wk (K branch only; Q/A are dead) ----------------
__global__ void fold_k(const float* __restrict__ Wa_d,
                       const float* __restrict__ Wk_d,
                       const float* __restrict__ bk_d) {
    for (int idx = threadIdx.x; idx < Cc*25 + 25; idx += blockDim.x) {
        if (idx < Cc*25) {
            int c = idx / 25, t = idx % 25;
            float s = 0.f;
            for (int ci = 0; ci < Cc; ci++)
                s += Wa_d[(Cc + ci)*25 + t] * Wk_d[ci*Cc + c];
            g_Wfk[idx] = s;
        } else {
            int t = idx - Cc*25;
            float s = 0.f;
            for (int ci = 0; ci < Cc; ci++)
                s += Wa_d[(Cc + ci)*25 + t] * bk_d[ci];
            g_bw[t] = s;
        }
    }
}

// ---------------- V = Wv * LN(x) + bv  (per-pixel GEMV, 2 px/thread) ----------------
__global__ void __launch_bounds__(128) v_k(const float* __restrict__ x,
        const float* __restrict__ gg, const float* __restrict__ bb,
        const float* __restrict__ Wv, const float* __restrict__ bv) {
    __shared__ float Ws[Cc*Cc];   // Ws[c][o] = Wv[o][c]
    __shared__ float bvs[Cc];
    int tid = threadIdx.x;
    for (int i = tid; i < Cc*Cc; i += 128) {
        int o = i & 63, c = i >> 6;
        Ws[c*Cc + o] = Wv[o*Cc + c];
    }
    if (tid < Cc) bvs[tid] = bv[tid];
    __syncthreads();
    int l = blockIdx.y;
    float mu = g_stats[l*2], rs = g_stats[l*2 + 1];
    int p0 = blockIdx.x * 256 + tid;
    const float* xl = x + (size_t)l * CHW;
    float a0[Cc], a1[Cc];
    #pragma unroll
    for (int o = 0; o < Cc; o++) { a0[o] = bvs[o]; a1[o] = bvs[o]; }
    for (int c = 0; c < Cc; c++) {
        int off = c*HW + p0;
        float h0 = (xl[off]     - mu)*rs*gg[off]     + bb[off];
        float h1 = (xl[off+128] - mu)*rs*gg[off+128] + bb[off+128];
        const float* wr = &Ws[c*Cc];
        #pragma unroll
        for (int o = 0; o < Cc; o++) {
            float w = wr[o];
            a0[o] += w * h0;
            a1[o] += w * h1;
        }
    }
    float* Vl = g_V + (size_t)l * CHW;
    #pragma unroll
    for (int o = 0; o < Cc; o++) {
        Vl[o*HW + p0]       = a0[o];
        Vl[o*HW + p0 + 128] = a1[o];
    }
}

// ---------------- B = conv5(LN(x), Wfk) + border bias ----------------
__global__ void conv_b_k(const float* __restrict__ x,
        const float* __restrict__ gg, const float* __restrict__ bb) {
    __shared__ float tile[12*36];
    __shared__ float wf[Cc*25];
    __shared__ float bw[25];
    int tid = threadIdx.x;
    for (int i = tid; i < Cc*25; i += 256) wf[i] = g_Wfk[i];
    if (tid < 25) bw[tid] = g_bw[tid];
    int l = blockIdx.z;
    float mu = g_stats[l*2], rs = g_stats[l*2 + 1];
    int x0 = blockIdx.x*32, y0 = blockIdx.y*8;
    int tx = tid & 31, ty = tid >> 5;
    const float* xl = x + (size_t)l*CHW;
    float acc = 0.f;
    for (int c = 0; c < Cc; c++) {
        __syncthreads();
        for (int i = tid; i < 12*36; i += 256) {
            int r = i / 36, cc = i % 36;
            int yy = y0 + r - 2, xx = x0 + cc - 2;
            float v = 0.f;
            if (yy >= 0 && yy < Hh && xx >= 0 && xx < Ww) {
                int off = c*HW + yy*Ww + xx;
                v = (xl[off] - mu)*rs*gg[off] + bb[off];
            }
            tile[i] = v;
        }
        __syncthreads();
        const float* wr = &wf[c*25];
        #pragma unroll
        for (int ky = 0; ky < 5; ky++)
            #pragma unroll
            for (int kx = 0; kx < 5; kx++)
                acc += wr[ky*5 + kx] * tile[(ty+ky)*36 + tx + kx];
    }
    float bias = 0.f;
    int px = x0 + tx, py = y0 + ty;
    #pragma unroll
    for (int ky = 0; ky < 5; ky++)
        #pragma unroll
        for (int kx = 0; kx < 5; kx++) {
            int yy = py + ky - 2, xx = px + kx - 2;
            if (yy >= 0 && yy < Hh && xx >= 0 && xx < Ww) bias += bw[ky*5 + kx];
        }
    g_B[l*HW + py*Ww + px] = acc + bias;
}

// ---------------- softmax over frames j (i-independent!) ----------------
__global__ void softmax_k() {
    int p = blockIdx.x*256 + threadIdx.x;
    float v[Lf];
    float m = -1e30f;
    #pragma unroll
    for (int j = 0; j < Lf; j++) { v[j] = g_B[j*HW + p]; m = fmaxf(m, v[j]); }
    float s = 0.f;
    #pragma unroll
    for (int j = 0; j < Lf; j++) { v[j] = expf(v[j] - m); s += v[j]; }
    float inv = 1.f / s;
    #pragma unroll
    for (int j = 0; j < Lf; j++) g_P[j*HW + p] = v[j] * inv;
}

// ---------------- attn[c,p] = sum_j P[j,p] V[j,c,p]; x[i] += attn (all i) ----------------
__global__ void attn_k(float* __restrict__ x) {
    int p = blockIdx.x*256 + threadIdx.x;
    int c = blockIdx.y;
    float acc = 0.f;
    #pragma unroll
    for (int j = 0; j < Lf; j++)
        acc += g_P[j*HW + p] * g_V[(size_t)j*CHW + c*HW + p];
    #pragma unroll
    for (int i = 0; i < Lf; i++) {
        size_t off = (size_t)i*CHW + c*HW + p;
        x[off] += acc;
    }
}

// ---------------- FFN stage 1: f1 = lrelu(W1 * LN(x) + b1), half (64 rows) per block.z ----------------
__global__ void __launch_bounds__(128) ffn1_k(const float* __restrict__ x,
        const float* __restrict__ gg, const float* __restrict__ bb,
        const float* __restrict__ W1, const float* __restrict__ b1) {
    __shared__ float Ws[64*Cc];
    __shared__ float b1s[64];
    int tid = threadIdx.x;
    int half = blockIdx.z;
    const float* W1h = W1 + half*64*Cc;
    for (int i = tid; i < 64*Cc; i += 128) {
        int o = i & 63, c = i >> 6;
        Ws[c*64 + o] = W1h[o*Cc + c];
    }
    if (tid < 64) b1s[tid] = b1[half*64 + tid];
    __syncthreads();
    int l = blockIdx.y;
    float mu = g_stats[l*2], rs = g_stats[l*2 + 1];
    int p0 = blockIdx.x*256 + tid;
    const float* xl = x + (size_t)l*CHW;
    float a0[64], a1[64];
    #pragma unroll
    for (int o = 0; o < 64; o++) { a0[o] = b1s[o]; a1[o] = b1s[o]; }
    for (int c = 0; c < Cc; c++) {
        int off = c*HW + p0;
        float h0 = (xl[off]     - mu)*rs*gg[off]     + bb[off];
        float h1 = (xl[off+128] - mu)*rs*gg[off+128] + bb[off+128];
        const float* wr = &Ws[c*64];
        #pragma unroll
        for (int o = 0; o < 64; o++) {
            float w = wr[o];
            a0[o] += w * h0;
            a1[o] += w * h1;
        }
    }
    float* F = g_F1 + (size_t)l*(2*Cc*HW) + (size_t)half*64*HW;
    #pragma unroll
    for (int o = 0; o < 64; o++) {
        float v0 = a0[o]; v0 = v0 > 0.f ? v0 : 0.01f*v0;
        float v1 = a1[o]; v1 = v1 > 0.f ? v1 : 0.01f*v1;
        F[o*HW + p0]       = v0;
        F[o*HW + p0 + 128] = v1;
    }
}

// ---------------- FFN stage 2: x += W2 * f1 + b2 ----------------
__global__ void __launch_bounds__(128) ffn2_k(float* __restrict__ x,
        const float* __restrict__ W2, const float* __restrict__ b2) {
    __shared__ float Ws[128*Cc];  // Ws[o][c] = W2[c][o]
    __shared__ float b2s[Cc];
    int tid = threadIdx.x;
    for (int i = tid; i < 128*Cc; i += 128) {
        int c = i & 63, o = i >> 6;
        Ws[o*Cc + c] = W2[c*128 + o];
    }
    if (tid < Cc) b2s[tid] = b2[tid];
    __syncthreads();
    int l = blockIdx.y;
    int p0 = blockIdx.x*256 + tid;
    const float* F = g_F1 + (size_t)l*(2*Cc*HW);
    float a0[Cc], a1[Cc];
    #pragma unroll
    for (int c = 0; c < Cc; c++) { a0[c] = b2s[c]; a1[c] = b2s[c]; }
    for (int o = 0; o < 128; o++) {
        float f0 = F[o*HW + p0];
        float f1v = F[o*HW + p0 + 128];
        const float* wr = &Ws[o*Cc];
        #pragma unroll
        for (int c = 0; c < Cc; c++) {
            float w = wr[c];
            a0[c] += w * f0;
            a1[c] += w * f1v;
        }
    }
    float* xl = x + (size_t)l*CHW;
    #pragma unroll
    for (int c = 0; c < Cc; c++) {
        xl[c*HW + p0]       += a0[c];
        xl[c*HW + p0 + 128] += a1[c];
    }
}

// ---------------- launch ----------------
extern "C" void kernel_launch(void* const* d_in, const int* in_sizes, int n_in,
                              void* d_out, int out_size) {
    const float* x_in = (const float*)d_in[0];
    const float* ln1g = (const float*)d_in[1];
    const float* ln1b = (const float*)d_in[2];
    // d_in[3]=Wq, d_in[4]=bq, d_in[10]=ba: dead (softmax over j cancels them)
    const float* Wk   = (const float*)d_in[5];
    const float* bk   = (const float*)d_in[6];
    const float* Wv   = (const float*)d_in[7];
    const float* bv   = (const float*)d_in[8];
    const float* Wa   = (const float*)d_in[9];
    const float* ln2g = (const float*)d_in[11];
    const float* ln2b = (const float*)d_in[12];
    const float* W1   = (const float*)d_in[13];
    const float* b1   = (const float*)d_in[14];
    const float* W2   = (const float*)d_in[15];
    const float* b2   = (const float*)d_in[16];
    float* x = (float*)d_out;

    cudaMemcpyAsync(x, x_in, sizeof(float)*(size_t)LCHW, cudaMemcpyDeviceToDevice);

    for (int d = 0; d < 4; d++) {
        ln_partial_k<<<dim3(NCHUNK, Lf), 256>>>(x);
        ln_final_k<<<1, 512>>>();
        fold_k<<<1, 256>>>(Wa + (size_t)d*2*Cc*25, Wk + (size_t)d*Cc*Cc, bk + (size_t)d*Cc);
        v_k<<<dim3(HW/256, Lf), 128>>>(x, ln1g + (size_t)d*CHW, ln1b + (size_t)d*CHW,
                                       Wv + (size_t)d*Cc*Cc, bv + (size_t)d*Cc);
        conv_b_k<<<dim3(Ww/32, Hh/8, Lf), 256>>>(x, ln1g + (size_t)d*CHW, ln1b + (size_t)d*CHW);
        softmax_k<<<HW/256, 256>>>();
        attn_k<<<dim3(HW/256, Cc), 256>>>(x);
        ln_partial_k<<<dim3(NCHUNK, Lf), 256>>>(x);
        ln_final_k<<<1, 512>>>();
        ffn1_k<<<dim3(HW/256, Lf, 2), 128>>>(x, ln2g + (size_t)d*CHW, ln2b + (size_t)d*CHW,
                                             W1 + (size_t)d*2*Cc*Cc, b1 + (size_t)d*2*Cc);
        ffn2_k<<<dim3(HW/256, Lf), 128>>>(x, W2 + (size_t)d*Cc*2*Cc, b2 + (size_t)d*Cc);
    }
}

// round 3
// speedup vs baseline: 1.5886x; 1.5886x over previous
#include <cuda_runtime.h>

#define Lf 16
#define Cc 64
#define Hh 128
#define Ww 128
#define HW (Hh*Ww)
#define CHW (Cc*HW)
#define LCHW (Lf*CHW)

// -------- scratch (static device globals) --------
__device__ float g_B[Lf*HW];       // pre-softmax scores
__device__ float g_attn[CHW];      // attention output (frame-independent!)
__device__ float g_stats[2*Lf];    // per-frame mean, rstd
__device__ float g_part[Lf*64*2];  // LN partial sums (64 chunks per frame)
__device__ float g_Wfk[Cc*25];     // folded conv weights
__device__ float g_bw[25];         // folded conv bias taps

// -------- packed fp32x2 helpers --------
__device__ __forceinline__ void fma2(unsigned long long &d, unsigned long long a, unsigned long long b) {
    asm("fma.rn.f32x2 %0, %1, %2, %0;" : "+l"(d) : "l"(a), "l"(b));
}
__device__ __forceinline__ unsigned long long pk(float lo, float hi) {
    unsigned long long d;
    asm("mov.b64 %0, {%1,%2};" : "=l"(d) : "f"(lo), "f"(hi));
    return d;
}
__device__ __forceinline__ void upk(float &lo, float &hi, unsigned long long d) {
    asm("mov.b64 {%0,%1}, %2;" : "=f"(lo), "=f"(hi) : "l"(d));
}

// -------- block reduce (256 threads) of (s, s2) -> g_part[(l*64+chunk)*2] --------
__device__ __forceinline__ void reduce_write(float s, float s2, int l, int chunk) {
    #pragma unroll
    for (int o = 16; o > 0; o >>= 1) {
        s  += __shfl_down_sync(0xffffffffu, s,  o);
        s2 += __shfl_down_sync(0xffffffffu, s2, o);
    }
    __shared__ float sh[8], sh2[8];
    int w = threadIdx.x >> 5, lane = threadIdx.x & 31;
    if (lane == 0) { sh[w] = s; sh2[w] = s2; }
    __syncthreads();
    if (w == 0 && lane < 8) {
        s = sh[lane]; s2 = sh2[lane];
        #pragma unroll
        for (int o = 4; o > 0; o >>= 1) {
            s  += __shfl_down_sync(0xffu, s,  o);
            s2 += __shfl_down_sync(0xffu, s2, o);
        }
        if (lane == 0) {
            g_part[(l*64 + chunk)*2]     = s;
            g_part[(l*64 + chunk)*2 + 1] = s2;
        }
    }
}

// ---------------- copy input + LN1 partials (layer 0) ----------------
__global__ void copy_stats_k(const float* __restrict__ xin, float* __restrict__ x) {
    int l = blockIdx.y, chunk = blockIdx.x;
    const float4* src = reinterpret_cast<const float4*>(xin + (size_t)l*CHW) + chunk*4096;
    float4* dst = reinterpret_cast<float4*>(x + (size_t)l*CHW) + chunk*4096;
    float s = 0.f, s2 = 0.f;
    #pragma unroll 4
    for (int i = threadIdx.x; i < 4096; i += 256) {
        float4 v = src[i];
        dst[i] = v;
        s  += v.x + v.y + v.z + v.w;
        s2 += v.x*v.x + v.y*v.y + v.z*v.z + v.w*v.w;
    }
    reduce_write(s, s2, l, chunk);
}

// ---------------- LN finalize (16 frames, 64 chunks each) ----------------
__global__ void ln_final_k() {
    int w = threadIdx.x >> 5, lane = threadIdx.x & 31;
    float s  = g_part[(w*64 + lane)*2]     + g_part[(w*64 + lane + 32)*2];
    float s2 = g_part[(w*64 + lane)*2 + 1] + g_part[(w*64 + lane + 32)*2 + 1];
    #pragma unroll
    for (int o = 16; o > 0; o >>= 1) {
        s  += __shfl_down_sync(0xffffffffu, s,  o);
        s2 += __shfl_down_sync(0xffffffffu, s2, o);
    }
    if (lane == 0) {
        float mu  = s / (float)CHW;
        float var = s2 / (float)CHW - mu*mu;
        g_stats[w*2]     = mu;
        g_stats[w*2 + 1] = rsqrtf(var + 1e-5f);
    }
}

// ---------------- fold 5x5 conv through Wk (K branch; Q/A/ba dead) ----------------
__global__ void fold_k(const float* __restrict__ Wa_d,
                       const float* __restrict__ Wk_d,
                       const float* __restrict__ bk_d) {
    for (int idx = threadIdx.x; idx < Cc*25 + 25; idx += blockDim.x) {
        if (idx < Cc*25) {
            int c = idx / 25, t = idx % 25;
            float s = 0.f;
            for (int ci = 0; ci < Cc; ci++)
                s += Wa_d[(Cc + ci)*25 + t] * Wk_d[ci*Cc + c];
            g_Wfk[idx] = s;
        } else {
            int t = idx - Cc*25;
            float s = 0.f;
            for (int ci = 0; ci < Cc; ci++)
                s += Wa_d[(Cc + ci)*25 + t] * bk_d[ci];
            g_bw[t] = s;
        }
    }
}

// ---------------- B = conv5(LN1(x), Wfk) + border bias ----------------
__global__ void conv_b_k(const float* __restrict__ x,
        const float* __restrict__ gg, const float* __restrict__ bb) {
    __shared__ float tile[4][12*36];
    __shared__ float wf[Cc*25];
    __shared__ float bwS[25];
    int tid = threadIdx.x;
    for (int i = tid; i < Cc*25; i += 256) wf[i] = g_Wfk[i];
    if (tid < 25) bwS[tid] = g_bw[tid];
    int l = blockIdx.z;
    float mu = g_stats[l*2], rs = g_stats[l*2 + 1];
    int x0 = blockIdx.x*32, y0 = blockIdx.y*8;
    int tx = tid & 31, ty = tid >> 5;
    const float* xl = x + (size_t)l*CHW;
    float acc = 0.f;
    for (int c0 = 0; c0 < Cc; c0 += 4) {
        __syncthreads();
        for (int i = tid; i < 4*432; i += 256) {
            int cc = i / 432;
            int rem = i - cc*432;
            int r = rem / 36, col = rem - r*36;
            int yy = y0 + r - 2, xx = x0 + col - 2;
            float v = 0.f;
            if (yy >= 0 && yy < Hh && xx >= 0 && xx < Ww) {
                int off = (c0+cc)*HW + yy*Ww + xx;
                v = (xl[off] - mu)*rs*gg[off] + bb[off];
            }
            tile[cc][rem] = v;
        }
        __syncthreads();
        #pragma unroll
        for (int cc = 0; cc < 4; cc++) {
            const float* wr = &wf[(c0+cc)*25];
            #pragma unroll
            for (int ky = 0; ky < 5; ky++)
                #pragma unroll
                for (int kx = 0; kx < 5; kx++)
                    acc += wr[ky*5 + kx] * tile[cc][(ty+ky)*36 + tx + kx];
        }
    }
    float bias = 0.f;
    int px = x0 + tx, py = y0 + ty;
    #pragma unroll
    for (int ky = 0; ky < 5; ky++)
        #pragma unroll
        for (int kx = 0; kx < 5; kx++) {
            int yy = py + ky - 2, xx = px + kx - 2;
            if (yy >= 0 && yy < Hh && xx >= 0 && xx < Ww) bias += bwS[ky*5 + kx];
        }
    g_B[l*HW + py*Ww + px] = acc + bias;
}

// ---------------- softmax + hbar + V-GEMV fused: attn[c,p] ----------------
// hbar[c,p] = sum_j P[j,p] * LN1(x)[j,c,p];  attn = Wv * hbar + bv
__global__ void __launch_bounds__(128) mega_k(const float* __restrict__ x,
        const float* __restrict__ gg, const float* __restrict__ bb,
        const float* __restrict__ Wv, const float* __restrict__ bv) {
    __shared__ float WvT[Cc*Cc];  // WvT[c][o] = Wv[o][c]
    __shared__ float bvs[Cc];
    int tid = threadIdx.x;
    for (int i = tid; i < Cc*Cc; i += 128) {
        int o = i >> 6, c = i & 63;
        WvT[c*Cc + o] = Wv[i];
    }
    if (tid < Cc) bvs[tid] = bv[tid];
    __syncthreads();
    int p = blockIdx.x*128 + tid;
    // softmax over frames
    float P[Lf]; float m = -1e30f;
    #pragma unroll
    for (int j = 0; j < Lf; j++) { P[j] = g_B[j*HW + p]; m = fmaxf(m, P[j]); }
    float ssum = 0.f;
    #pragma unroll
    for (int j = 0; j < Lf; j++) { P[j] = expf(P[j] - m); ssum += P[j]; }
    float inv = 1.f / ssum;
    float q[Lf]; float mm = 0.f;
    #pragma unroll
    for (int j = 0; j < Lf; j++) {
        float pj = P[j] * inv;
        float rs = g_stats[j*2 + 1], mu = g_stats[j*2];
        q[j] = pj * rs;
        mm += pj * mu * rs;
    }
    // hbar
    float hbar[Cc];
    #pragma unroll 4
    for (int c = 0; c < Cc; c++) {
        float s = -mm;
        #pragma unroll
        for (int j = 0; j < Lf; j++)
            s += q[j] * x[(size_t)j*CHW + c*HW + p];
        hbar[c] = s * gg[c*HW + p] + bb[c*HW + p];
    }
    // attn = Wv * hbar + bv
    float acc[Cc];
    #pragma unroll
    for (int o = 0; o < Cc; o++) acc[o] = bvs[o];
    for (int c = 0; c < Cc; c++) {
        float h = hbar[c];
        const float4* wr = reinterpret_cast<const float4*>(&WvT[c*Cc]);
        #pragma unroll
        for (int o4 = 0; o4 < 16; o4++) {
            float4 w = wr[o4];
            acc[o4*4]   += w.x * h;
            acc[o4*4+1] += w.y * h;
            acc[o4*4+2] += w.z * h;
            acc[o4*4+3] += w.w * h;
        }
    }
    #pragma unroll
    for (int o = 0; o < Cc; o++) g_attn[o*HW + p] = acc[o];
}

// ---------------- x[l] += attn (all frames) + LN2 partials ----------------
__global__ void addres_k(float* __restrict__ x) {
    int l = blockIdx.y, chunk = blockIdx.x;
    const float4* at = reinterpret_cast<const float4*>(g_attn) + chunk*4096;
    float4* xd = reinterpret_cast<float4*>(x + (size_t)l*CHW) + chunk*4096;
    float s = 0.f, s2 = 0.f;
    #pragma unroll 4
    for (int i = threadIdx.x; i < 4096; i += 256) {
        float4 v = xd[i];
        float4 a = at[i];
        v.x += a.x; v.y += a.y; v.z += a.z; v.w += a.w;
        xd[i] = v;
        s  += v.x + v.y + v.z + v.w;
        s2 += v.x*v.x + v.y*v.y + v.z*v.z + v.w*v.w;
    }
    reduce_write(s, s2, l, chunk);
}

// ---------------- fused FFN: x += W2*lrelu(W1*LN2(x)+b1)+b2, + next LN1 partials ----------------
// W1 staged as Ws[c*132+o] (o=0..127), then W2 restaged as Ws[o*68+c] (c=0..63)
__global__ void __launch_bounds__(256, 1) ffn_k(float* __restrict__ x,
        const float* __restrict__ gg, const float* __restrict__ bb,
        const float* __restrict__ W1, const float* __restrict__ b1,
        const float* __restrict__ W2, const float* __restrict__ b2) {
    __shared__ __align__(16) float Ws[128*68];   // 34.8 KB, reused for W1 then W2
    __shared__ float b1s[128];
    __shared__ float b2s[64];
    int tid = threadIdx.x;
    // stage W1 transposed: Ws[c*132+o] = W1[o*64+c]
    for (int i = tid; i < 128*64; i += 256) {
        int o = i >> 6, c = i & 63;
        Ws[c*132 + o] = W1[i];
    }
    if (tid < 128) b1s[tid] = b1[tid];
    if (tid < 64)  b2s[tid] = b2[tid];
    __syncthreads();

    int l = blockIdx.y;
    int p = blockIdx.x*256 + tid;
    float mu = g_stats[l*2], rs = g_stats[l*2 + 1];
    float* xl = x + (size_t)l*CHW;

    // phase 1: f1 pairs (o,o+1) packed
    unsigned long long f1[64];
    #pragma unroll
    for (int k = 0; k < 64; k++) f1[k] = pk(b1s[2*k], b1s[2*k+1]);
    for (int c0 = 0; c0 < Cc; c0 += 8) {
        float hv[8];
        #pragma unroll
        for (int u = 0; u < 8; u++) {
            int off = (c0+u)*HW + p;
            hv[u] = (xl[off] - mu)*rs*gg[off] + bb[off];
        }
        #pragma unroll
        for (int u = 0; u < 8; u++) {
            unsigned long long hd = pk(hv[u], hv[u]);
            const ulonglong2* wr = reinterpret_cast<const ulonglong2*>(&Ws[(c0+u)*132]);
            #pragma unroll
            for (int k = 0; k < 32; k++) {
                ulonglong2 w = wr[k];
                fma2(f1[2*k],   w.x, hd);
                fma2(f1[2*k+1], w.y, hd);
            }
        }
    }
    __syncthreads();
    // restage W2 transposed+paired: Ws[o*68+c] = W2[c*128+o]
    for (int i = tid; i < 64*128; i += 256) {
        int c = i >> 7, o = i & 127;
        Ws[o*68 + c] = W2[i];
    }
    __syncthreads();

    // phase 2: out pairs (c,c+1) packed
    unsigned long long out2[32];
    #pragma unroll
    for (int k = 0; k < 32; k++) out2[k] = pk(b2s[2*k], b2s[2*k+1]);
    #pragma unroll 4
    for (int k = 0; k < 64; k++) {
        float lo, hi;
        upk(lo, hi, f1[k]);
        lo = lo > 0.f ? lo : 0.01f*lo;
        hi = hi > 0.f ? hi : 0.01f*hi;
        unsigned long long dlo = pk(lo, lo), dhi = pk(hi, hi);
        const ulonglong2* wr0 = reinterpret_cast<const ulonglong2*>(&Ws[(2*k)*68]);
        const ulonglong2* wr1 = reinterpret_cast<const ulonglong2*>(&Ws[(2*k+1)*68]);
        #pragma unroll
        for (int m2 = 0; m2 < 16; m2++) {
            ulonglong2 w = wr0[m2];
            fma2(out2[2*m2],   w.x, dlo);
            fma2(out2[2*m2+1], w.y, dlo);
        }
        #pragma unroll
        for (int m2 = 0; m2 < 16; m2++) {
            ulonglong2 w = wr1[m2];
            fma2(out2[2*m2],   w.x, dhi);
            fma2(out2[2*m2+1], w.y, dhi);
        }
    }

    // phase 3: residual add + next-LN partial sums
    float s = 0.f, s2 = 0.f;
    #pragma unroll
    for (int k = 0; k < 32; k++) {
        float o0, o1;
        upk(o0, o1, out2[k]);
        int off0 = (2*k)*HW + p;
        int off1 = off0 + HW;
        float v0 = xl[off0] + o0;
        float v1 = xl[off1] + o1;
        xl[off0] = v0;
        xl[off1] = v1;
        s += v0 + v1;
        s2 += v0*v0 + v1*v1;
    }
    reduce_write(s, s2, l, blockIdx.x);
}

// ---------------- launch ----------------
extern "C" void kernel_launch(void* const* d_in, const int* in_sizes, int n_in,
                              void* d_out, int out_size) {
    const float* x_in = (const float*)d_in[0];
    const float* ln1g = (const float*)d_in[1];
    const float* ln1b = (const float*)d_in[2];
    // d_in[3]=Wq, d_in[4]=bq, d_in[10]=ba: dead (softmax over j cancels them)
    const float* Wk   = (const float*)d_in[5];
    const float* bk   = (const float*)d_in[6];
    const float* Wv   = (const float*)d_in[7];
    const float* bv   = (const float*)d_in[8];
    const float* Wa   = (const float*)d_in[9];
    const float* ln2g = (const float*)d_in[11];
    const float* ln2b = (const float*)d_in[12];
    const float* W1   = (const float*)d_in[13];
    const float* b1   = (const float*)d_in[14];
    const float* W2   = (const float*)d_in[15];
    const float* b2   = (const float*)d_in[16];
    float* x = (float*)d_out;

    copy_stats_k<<<dim3(64, Lf), 256>>>(x_in, x);   // copy + layer0 ln1 partials

    for (int d = 0; d < 4; d++) {
        ln_final_k<<<1, 512>>>();
        fold_k<<<1, 256>>>(Wa + (size_t)d*2*Cc*25, Wk + (size_t)d*Cc*Cc, bk + (size_t)d*Cc);
        conv_b_k<<<dim3(Ww/32, Hh/8, Lf), 256>>>(x, ln1g + (size_t)d*CHW, ln1b + (size_t)d*CHW);
        mega_k<<<HW/128, 128>>>(x, ln1g + (size_t)d*CHW, ln1b + (size_t)d*CHW,
                                Wv + (size_t)d*Cc*Cc, bv + (size_t)d*Cc);
        addres_k<<<dim3(64, Lf), 256>>>(x);         // += attn, ln2 partials
        ln_final_k<<<1, 512>>>();
        ffn_k<<<dim3(HW/256, Lf), 256>>>(x, ln2g + (size_t)d*CHW, ln2b + (size_t)d*CHW,
                                         W1 + (size_t)d*2*Cc*Cc, b1 + (size_t)d*2*Cc,
                                         W2 + (size_t)d*Cc*2*Cc, b2 + (size_t)d*Cc);
    }
}